// round 5
// baseline (speedup 1.0000x reference)
#include <cuda_runtime.h>
#include <cstdint>

// W=1048576 windows, K=49, C=32 output channels.
// Structure: 64-thread blocks (2 warps). warp w handles channel pairs [8w, 8w+8).
// Each thread: TW=8 windows x CP=8 channel pairs (f32x2) = 64 accumulators.
#define KW 49
#define CP 8               // channel pairs per thread
#define TW 8               // windows per thread
#define THREADS 64
#define WPB 256            // windows per block (32 lanes * TW)
#define WTOT 1048576u

// dynamic smem: sx[WPB*KW] f32 | sw[KW][8] ulonglong2 (16 pairs) | sb[16] u64
#define SX_FLOATS (WPB * KW)                        // 12544
#define SX_BYTES  (SX_FLOATS * 4)                   // 50176
#define SW_BYTES  (KW * 8 * 16)                     // 6272
#define SMEM_BYTES (SX_BYTES + SW_BYTES + 16 * 8)   // 56576

__device__ __forceinline__ unsigned long long pack2(float lo, float hi) {
    unsigned long long r;
    asm("mov.b64 %0, {%1, %2};" : "=l"(r) : "f"(lo), "f"(hi));
    return r;
}

__device__ __forceinline__ unsigned long long ffma2(unsigned long long a,
                                                    unsigned long long b,
                                                    unsigned long long c) {
    unsigned long long d;
    asm("fma.rn.f32x2 %0, %1, %2, %3;" : "=l"(d) : "l"(a), "l"(b), "l"(c));
    return d;
}

__global__ __launch_bounds__(THREADS)
void conv_im2col_kernel(const float* __restrict__ x,     // [W, 49]
                        const float* __restrict__ wgt,   // [32, 49]
                        const float* __restrict__ bias,  // [32]
                        float* __restrict__ out)         // [32 * W]
{
    extern __shared__ __align__(16) unsigned char smem_raw[];
    float*              sx = reinterpret_cast<float*>(smem_raw);
    ulonglong2*         sw = reinterpret_cast<ulonglong2*>(smem_raw + SX_BYTES);
    unsigned long long* sb = reinterpret_cast<unsigned long long*>(smem_raw + SX_BYTES + SW_BYTES);

    const unsigned tid  = threadIdx.x;
    const unsigned wid  = tid >> 5;          // warp 0: pairs 0-7, warp 1: pairs 8-15
    const unsigned lane = tid & 31;

    // --- Stage weights (16 packed channel pairs per k) + bias ---
    {
        unsigned long long* swf = reinterpret_cast<unsigned long long*>(sw);
        for (unsigned i = tid; i < KW * 16; i += THREADS) {
            unsigned k = i >> 4, p = i & 15;
            swf[k * 16 + p] = pack2(wgt[(2 * p) * KW + k], wgt[(2 * p + 1) * KW + k]);
        }
        if (tid < 16) sb[tid] = pack2(bias[2 * tid], bias[2 * tid + 1]);
    }

    // --- Stage x tile: 256 contiguous rows, coalesced LDG.128 ---
    {
        const float4* src = reinterpret_cast<const float4*>(
            x + (size_t)blockIdx.x * (WPB * KW));
        float4* dst = reinterpret_cast<float4*>(sx);
#pragma unroll
        for (unsigned i = 0; i < SX_FLOATS / 4 / THREADS; i++)   // 49 iters
            dst[tid + i * THREADS] = src[tid + i * THREADS];
    }
    __syncthreads();

    // --- Accumulators: 8 windows x 8 pairs ---
    unsigned long long acc[TW][CP];
#pragma unroll
    for (int j = 0; j < TW; j++)
#pragma unroll
        for (int p = 0; p < CP; p++)
            acc[j][p] = sb[wid * CP + p];

    // x row bases: window = base + lane + 32*j
    unsigned row[TW];
#pragma unroll
    for (int j = 0; j < TW; j++) row[j] = (lane + 32u * j) * KW;

    const unsigned swq = wid * 4;   // this warp's 4 LDS.128 slots per k

#pragma unroll 7
    for (int k = 0; k < KW; k++) {
        unsigned long long xv[TW];
#pragma unroll
        for (int j = 0; j < TW; j++) {
            float v = sx[row[j] + k];        // LDS.32, stride 49 -> conflict-free
            xv[j] = pack2(v, v);
        }
#pragma unroll
        for (int q = 0; q < 4; q++) {
            ulonglong2 w2 = sw[k * 8 + swq + q];   // LDS.128 broadcast: 2 pairs
#pragma unroll
            for (int j = 0; j < TW; j++) {
                acc[j][2 * q]     = ffma2(xv[j], w2.x, acc[j][2 * q]);
                acc[j][2 * q + 1] = ffma2(xv[j], w2.y, acc[j][2 * q + 1]);
            }
        }
    }

    // --- Coalesced stores: out[c * W + w], lanes consecutive in w ---
    const unsigned wbase = blockIdx.x * WPB + lane;
#pragma unroll
    for (int j = 0; j < TW; j++) {
        const unsigned w = wbase + 32u * j;
#pragma unroll
        for (int p = 0; p < CP; p++) {
            const unsigned c = 2 * (wid * CP + p);
            float lo, hi;
            asm("mov.b64 {%0, %1}, %2;" : "=f"(lo), "=f"(hi) : "l"(acc[j][p]));
            out[c * WTOT + w]       = lo;
            out[(c + 1) * WTOT + w] = hi;
        }
    }
}

extern "C" void kernel_launch(void* const* d_in, const int* in_sizes, int n_in,
                              void* d_out, int out_size) {
    (void)in_sizes; (void)n_in; (void)out_size;
    const float* x    = (const float*)d_in[0];   // enc_x [1048576, 49]
    const float* wgt  = (const float*)d_in[1];   // weight [32, 7, 7]
    const float* bias = (const float*)d_in[2];   // bias [32]
    float* out = (float*)d_out;

    cudaFuncSetAttribute(conv_im2col_kernel,
                         cudaFuncAttributeMaxDynamicSharedMemorySize, SMEM_BYTES);

    const unsigned nblocks = WTOT / WPB;         // 4096
    conv_im2col_kernel<<<nblocks, THREADS, SMEM_BYTES>>>(x, wgt, bias, out);
}

// round 7
// speedup vs baseline: 1.0800x; 1.0800x over previous
#include <cuda_runtime.h>
#include <cstdint>

// W=1048576 windows, K=49, C=32 output channels.
// Block = 128 threads = 4 warps sharing one 256-window tile.
// Warp w owns channel pairs [4w, 4w+4) (8 channels). Thread: TW=8 windows x
// CP=4 channel pairs = 32 f32x2 accumulators (64 regs) -> 128-reg budget, 4 blocks/SM.
#define KW 49
#define CP 4               // channel pairs per thread (per warp)
#define TW 8               // windows per thread
#define THREADS 128
#define WPB 256            // windows per block
#define WTOT 1048576u

// dynamic smem: sx[WPB*KW] f32 | sw[KW][8] ulonglong2 (16 pairs) | sb[16] u64
#define SX_FLOATS (WPB * KW)                        // 12544
#define SX_BYTES  (SX_FLOATS * 4)                   // 50176
#define SW_BYTES  (KW * 8 * 16)                     // 6272
#define SMEM_BYTES (SX_BYTES + SW_BYTES + 16 * 8)   // 56576

__device__ __forceinline__ unsigned long long pack2(float lo, float hi) {
    unsigned long long r;
    asm("mov.b64 %0, {%1, %2};" : "=l"(r) : "f"(lo), "f"(hi));
    return r;
}

__device__ __forceinline__ unsigned long long ffma2(unsigned long long a,
                                                    unsigned long long b,
                                                    unsigned long long c) {
    unsigned long long d;
    asm("fma.rn.f32x2 %0, %1, %2, %3;" : "=l"(d) : "l"(a), "l"(b), "l"(c));
    return d;
}

__global__ __launch_bounds__(THREADS, 4)
void conv_im2col_kernel(const float* __restrict__ x,     // [W, 49]
                        const float* __restrict__ wgt,   // [32, 49]
                        const float* __restrict__ bias,  // [32]
                        float* __restrict__ out)         // [32 * W]
{
    extern __shared__ __align__(16) unsigned char smem_raw[];
    float*              sx = reinterpret_cast<float*>(smem_raw);
    ulonglong2*         sw = reinterpret_cast<ulonglong2*>(smem_raw + SX_BYTES);
    unsigned long long* sb = reinterpret_cast<unsigned long long*>(smem_raw + SX_BYTES + SW_BYTES);

    const unsigned tid  = threadIdx.x;
    const unsigned wid  = tid >> 5;          // channel group 0..3 -> pairs [4*wid, 4*wid+4)
    const unsigned lane = tid & 31;

    // --- Stage weights (16 packed channel pairs per k) + bias ---
    {
        unsigned long long* swf = reinterpret_cast<unsigned long long*>(sw);
        for (unsigned i = tid; i < KW * 16; i += THREADS) {
            unsigned k = i >> 4, p = i & 15;
            swf[k * 16 + p] = pack2(wgt[(2 * p) * KW + k], wgt[(2 * p + 1) * KW + k]);
        }
        if (tid < 16) sb[tid] = pack2(bias[2 * tid], bias[2 * tid + 1]);
    }

    // --- Stage x tile: 256 contiguous rows, fully coalesced LDG.128 ---
    {
        const float4* src = reinterpret_cast<const float4*>(
            x + (size_t)blockIdx.x * (WPB * KW));
        float4* dst = reinterpret_cast<float4*>(sx);
#pragma unroll
        for (unsigned i = 0; i < SX_FLOATS / 4 / THREADS; i++)   // 24 iters
            dst[tid + i * THREADS] = src[tid + i * THREADS];
        // remainder: 3136 = 24*128 + 64
        if (tid < 64)
            dst[tid + (SX_FLOATS / 4 / THREADS) * THREADS] =
                src[tid + (SX_FLOATS / 4 / THREADS) * THREADS];
    }
    __syncthreads();

    // --- Accumulators: 8 windows x 4 pairs (64 regs) ---
    unsigned long long acc[TW][CP];
#pragma unroll
    for (int j = 0; j < TW; j++)
#pragma unroll
        for (int p = 0; p < CP; p++)
            acc[j][p] = sb[wid * CP + p];

    // x row bases: window = blockbase + lane + 32*j (same for all 4 warps)
    unsigned row[TW];
#pragma unroll
    for (int j = 0; j < TW; j++) row[j] = (lane + 32u * j) * KW;

    const unsigned swq = wid * 2;   // this warp's 2 LDS.128 slots per k

#pragma unroll 7
    for (int k = 0; k < KW; k++) {
        unsigned long long xv[TW];
#pragma unroll
        for (int j = 0; j < TW; j++) {
            float v = sx[row[j] + k];        // LDS.32, stride 49 -> conflict-free
            xv[j] = pack2(v, v);
        }
#pragma unroll
        for (int q = 0; q < 2; q++) {
            ulonglong2 w2 = sw[k * 8 + swq + q];   // LDS.128 broadcast: 2 pairs
#pragma unroll
            for (int j = 0; j < TW; j++) {
                acc[j][2 * q]     = ffma2(xv[j], w2.x, acc[j][2 * q]);
                acc[j][2 * q + 1] = ffma2(xv[j], w2.y, acc[j][2 * q + 1]);
            }
        }
    }

    // --- Coalesced stores: out[c * W + w], lanes consecutive in w ---
    const unsigned wbase = blockIdx.x * WPB + lane;
#pragma unroll
    for (int j = 0; j < TW; j++) {
        const unsigned w = wbase + 32u * j;
#pragma unroll
        for (int p = 0; p < CP; p++) {
            const unsigned c = 2 * (wid * CP + p);
            float lo, hi;
            asm("mov.b64 {%0, %1}, %2;" : "=f"(lo), "=f"(hi) : "l"(acc[j][p]));
            out[c * WTOT + w]       = lo;
            out[(c + 1) * WTOT + w] = hi;
        }
    }
}

extern "C" void kernel_launch(void* const* d_in, const int* in_sizes, int n_in,
                              void* d_out, int out_size) {
    (void)in_sizes; (void)n_in; (void)out_size;
    const float* x    = (const float*)d_in[0];   // enc_x [1048576, 49]
    const float* wgt  = (const float*)d_in[1];   // weight [32, 7, 7]
    const float* bias = (const float*)d_in[2];   // bias [32]
    float* out = (float*)d_out;

    cudaFuncSetAttribute(conv_im2col_kernel,
                         cudaFuncAttributeMaxDynamicSharedMemorySize, SMEM_BYTES);

    const unsigned nblocks = WTOT / WPB;         // 4096
    conv_im2col_kernel<<<nblocks, THREADS, SMEM_BYTES>>>(x, wgt, bias, out);
}